// round 1
// baseline (speedup 1.0000x reference)
#include <cuda_runtime.h>

#define PI_F 3.14159265358979323846f
#define FULL 0xffffffffu

// ---------------------------------------------------------------------------
// State layout: amplitude index i = (lane << 5) | l,  i bit (9-q) = qubit q.
//   qubits 0..4  -> lane bits 4..0  (lane mask K = 1 << (4-q))
//   qubits 5..9  -> local bits 4..0 (local mask M = 1 << (9-q))
// Each thread holds 32 complex amps in registers (ar[], ai[]).
// ---------------------------------------------------------------------------

template<int M>
__device__ __forceinline__ void ry_local(float (&ar)[32], float (&ai)[32], float c, float s) {
#pragma unroll
    for (int l = 0; l < 32; ++l) if (!(l & M)) {
        const int h = l | M;
        float r0 = ar[l], i0 = ai[l], r1 = ar[h], i1 = ai[h];
        ar[l] = c * r0 - s * r1;  ai[l] = c * i0 - s * i1;
        ar[h] = s * r0 + c * r1;  ai[h] = s * i0 + c * i1;
    }
}

template<int M>
__device__ __forceinline__ void rx_local(float (&ar)[32], float (&ai)[32], float c, float s) {
#pragma unroll
    for (int l = 0; l < 32; ++l) if (!(l & M)) {
        const int h = l | M;
        float r0 = ar[l], i0 = ai[l], r1 = ar[h], i1 = ai[h];
        // new0 = c*a0 - i*s*a1 ; new1 = c*a1 - i*s*a0
        ar[l] = c * r0 + s * i1;  ai[l] = c * i0 - s * r1;
        ar[h] = c * r1 + s * i0;  ai[h] = c * i1 - s * r0;
    }
}

template<int M>
__device__ __forceinline__ void rz_local(float (&ar)[32], float (&ai)[32], float c, float s) {
#pragma unroll
    for (int l = 0; l < 32; ++l) {
        // bit==0: *(c - i s)   bit==1: *(c + i s)
        float t = (l & M) ? s : -s;
        float r = ar[l], i = ai[l];
        ar[l] = c * r - t * i;
        ai[l] = c * i + t * r;
    }
}

template<int K>
__device__ __forceinline__ void ry_lane(float (&ar)[32], float (&ai)[32], float c, float s, unsigned lane) {
    // lo: c*a - s*p   hi: c*a + s*p
    float t = (lane & K) ? s : -s;
#pragma unroll
    for (int l = 0; l < 32; ++l) {
        float pr = __shfl_xor_sync(FULL, ar[l], K);
        float pi = __shfl_xor_sync(FULL, ai[l], K);
        ar[l] = fmaf(t, pr, c * ar[l]);
        ai[l] = fmaf(t, pi, c * ai[l]);
    }
}

template<int K>
__device__ __forceinline__ void rx_lane(float (&ar)[32], float (&ai)[32], float c, float s, unsigned lane) {
    // symmetric: new = c*a - i*s*p for both halves
    (void)lane;
#pragma unroll
    for (int l = 0; l < 32; ++l) {
        float pr = __shfl_xor_sync(FULL, ar[l], K);
        float pi = __shfl_xor_sync(FULL, ai[l], K);
        ar[l] = fmaf( s, pi, c * ar[l]);
        ai[l] = fmaf(-s, pr, c * ai[l]);
    }
}

template<int K>
__device__ __forceinline__ void rz_lane(float (&ar)[32], float (&ai)[32], float c, float s, unsigned lane) {
    float t = (lane & K) ? s : -s;
#pragma unroll
    for (int l = 0; l < 32; ++l) {
        float r = ar[l], i = ai[l];
        ar[l] = c * r - t * i;
        ai[l] = c * i + t * r;
    }
}

// CNOT, control & target both local bits
template<int CM, int TM>
__device__ __forceinline__ void cnot_ll(float (&ar)[32], float (&ai)[32]) {
#pragma unroll
    for (int l = 0; l < 32; ++l) if ((l & CM) && !(l & TM)) {
        const int h = l | TM;
        float tr = ar[l]; ar[l] = ar[h]; ar[h] = tr;
        float ti = ai[l]; ai[l] = ai[h]; ai[h] = ti;
    }
}

// CNOT, control = lane bit CK, target = local bit TM (no shuffle needed)
template<int CK, int TM>
__device__ __forceinline__ void cnot_lane_local(float (&ar)[32], float (&ai)[32], unsigned lane) {
    if (lane & CK) {
#pragma unroll
        for (int l = 0; l < 32; ++l) if (!(l & TM)) {
            const int h = l | TM;
            float tr = ar[l]; ar[l] = ar[h]; ar[h] = tr;
            float ti = ai[l]; ai[l] = ai[h]; ai[h] = ti;
        }
    }
}

// CNOT, control & target both lane bits (conditional exchange via shfl)
template<int CK, int TK>
__device__ __forceinline__ void cnot_lane_lane(float (&ar)[32], float (&ai)[32], unsigned lane) {
    const bool ctrl = (lane & CK) != 0;
#pragma unroll
    for (int l = 0; l < 32; ++l) {
        float pr = __shfl_xor_sync(FULL, ar[l], TK);
        float pi = __shfl_xor_sync(FULL, ai[l], TK);
        if (ctrl) { ar[l] = pr; ai[l] = pi; }
    }
}

// CNOT, control = local bit CM, target = lane bit TK (all lanes exchange)
template<int CM, int TK>
__device__ __forceinline__ void cnot_local_lane(float (&ar)[32], float (&ai)[32]) {
#pragma unroll
    for (int l = 0; l < 32; ++l) if (l & CM) {
        ar[l] = __shfl_xor_sync(FULL, ar[l], TK);
        ai[l] = __shfl_xor_sync(FULL, ai[l], TK);
    }
}

__global__ void __launch_bounds__(256)
qsim_kernel(const float* __restrict__ x, const float* __restrict__ w,
            float* __restrict__ out)
{
    const unsigned lane = threadIdx.x & 31u;
    const int warp = blockIdx.x * (blockDim.x >> 5) + (threadIdx.x >> 5);
    const float* xb = x + warp * 10;

    // Data-encoding half-angle cos/sin (reused every layer)
    float cx[10], sx[10];
#pragma unroll
    for (int q = 0; q < 10; ++q) {
        float v = fminf(fmaxf(xb[q], -PI_F), PI_F);
        __sincosf(0.5f * v, &sx[q], &cx[q]);
    }

    // |0...0>
    float ar[32], ai[32];
#pragma unroll
    for (int l = 0; l < 32; ++l) { ar[l] = 0.f; ai[l] = 0.f; }
    if (lane == 0) ar[0] = 1.f;

    for (int layer = 0; layer < 4; ++layer) {
        const float* wl = w + layer * 30;

        // -- data encoding RY(x_q) on every qubit --
        ry_lane<16>(ar, ai, cx[0], sx[0], lane);
        ry_lane< 8>(ar, ai, cx[1], sx[1], lane);
        ry_lane< 4>(ar, ai, cx[2], sx[2], lane);
        ry_lane< 2>(ar, ai, cx[3], sx[3], lane);
        ry_lane< 1>(ar, ai, cx[4], sx[4], lane);
        ry_local<16>(ar, ai, cx[5], sx[5]);
        ry_local< 8>(ar, ai, cx[6], sx[6]);
        ry_local< 4>(ar, ai, cx[7], sx[7]);
        ry_local< 2>(ar, ai, cx[8], sx[8]);
        ry_local< 1>(ar, ai, cx[9], sx[9]);

        // -- parameterized RX,RY,RZ per qubit --
        float c0, s0, c1, s1, c2, s2;
#define ROT_LANE(Q, K)                                         \
        __sincosf(0.5f * wl[(Q)*3 + 0], &s0, &c0);             \
        __sincosf(0.5f * wl[(Q)*3 + 1], &s1, &c1);             \
        __sincosf(0.5f * wl[(Q)*3 + 2], &s2, &c2);             \
        rx_lane<K>(ar, ai, c0, s0, lane);                      \
        ry_lane<K>(ar, ai, c1, s1, lane);                      \
        rz_lane<K>(ar, ai, c2, s2, lane);
        ROT_LANE(0, 16) ROT_LANE(1, 8) ROT_LANE(2, 4) ROT_LANE(3, 2) ROT_LANE(4, 1)
#undef ROT_LANE
#define ROT_LOCAL(Q, M)                                        \
        __sincosf(0.5f * wl[(Q)*3 + 0], &s0, &c0);             \
        __sincosf(0.5f * wl[(Q)*3 + 1], &s1, &c1);             \
        __sincosf(0.5f * wl[(Q)*3 + 2], &s2, &c2);             \
        rx_local<M>(ar, ai, c0, s0);                           \
        ry_local<M>(ar, ai, c1, s1);                           \
        rz_local<M>(ar, ai, c2, s2);
        ROT_LOCAL(5, 16) ROT_LOCAL(6, 8) ROT_LOCAL(7, 4) ROT_LOCAL(8, 2) ROT_LOCAL(9, 1)
#undef ROT_LOCAL

        // -- CNOT ring (order matters) --
        cnot_lane_lane<16, 8>(ar, ai, lane);   // (0,1)
        cnot_lane_lane< 8, 4>(ar, ai, lane);   // (1,2)
        cnot_lane_lane< 4, 2>(ar, ai, lane);   // (2,3)
        cnot_lane_lane< 2, 1>(ar, ai, lane);   // (3,4)
        cnot_lane_local<1, 16>(ar, ai, lane);  // (4,5)
        cnot_ll<16, 8>(ar, ai);                // (5,6)
        cnot_ll< 8, 4>(ar, ai);                // (6,7)
        cnot_ll< 4, 2>(ar, ai);                // (7,8)
        cnot_ll< 2, 1>(ar, ai);                // (8,9)
        cnot_local_lane<1, 16>(ar, ai);        // (9,0)
    }

    // -- measurement: <Z_q> --
    float tot = 0.f, z5 = 0.f, z6 = 0.f, z7 = 0.f, z8 = 0.f, z9 = 0.f;
#pragma unroll
    for (int l = 0; l < 32; ++l) {
        float p = ar[l] * ar[l] + ai[l] * ai[l];
        tot += p;
        z5 += (l & 16) ? -p : p;
        z6 += (l &  8) ? -p : p;
        z7 += (l &  4) ? -p : p;
        z8 += (l &  2) ? -p : p;
        z9 += (l &  1) ? -p : p;
    }
    float z[10];
    z[0] = (lane & 16) ? -tot : tot;
    z[1] = (lane &  8) ? -tot : tot;
    z[2] = (lane &  4) ? -tot : tot;
    z[3] = (lane &  2) ? -tot : tot;
    z[4] = (lane &  1) ? -tot : tot;
    z[5] = z5; z[6] = z6; z[7] = z7; z[8] = z8; z[9] = z9;

#pragma unroll
    for (int q = 0; q < 10; ++q) {
#pragma unroll
        for (int k = 16; k >= 1; k >>= 1)
            z[q] += __shfl_xor_sync(FULL, z[q], k);
    }
    if (lane == 0) {
#pragma unroll
        for (int q = 0; q < 10; ++q)
            out[warp * 10 + q] = z[q];
    }
}

extern "C" void kernel_launch(void* const* d_in, const int* in_sizes, int n_in,
                              void* d_out, int out_size) {
    // metadata order: inputs [4096,10] f32, weights [4,10,3] f32 — but detect
    // by size to be robust.
    const float* a = (const float*)d_in[0];
    const float* b = (const float*)d_in[1];
    const float* x = a;
    const float* w = b;
    if (n_in >= 2 && in_sizes[0] == 120 && in_sizes[1] == 40960) { x = b; w = a; }
    float* out = (float*)d_out;
    // 4096 warps, 8 warps per block
    qsim_kernel<<<512, 256>>>(x, w, out);
}

// round 2
// speedup vs baseline: 1.8684x; 1.8684x over previous
#include <cuda_runtime.h>

#define PI_F 3.14159265358979323846f
#define FULL 0xffffffffu

// ---------------------------------------------------------------------------
// State layout: amplitude index i = (lane << 5) | l,  i bit (9-q) = qubit q.
//   qubits 0..4  -> lane bits 4..0  (lane mask K = 1 << (4-q))
//   qubits 5..9  -> local bits 4..0 (local mask M = 1 << (9-q))
// Each thread holds 32 complex amps in registers.
//
// All single-qubit gates are SU(2): U = [[a, b],[-conj(b), conj(a)]] with
// a = (ar, ai), b = (br, bi). Per layer per qubit the full rotation block
// RZ(w2)*RY(w1)*RX(w0)*RY(x_q) is ONE such U. The weight-only part
// W = RZ*RY*RX is batch-independent and precomputed by prep_kernel.
// ---------------------------------------------------------------------------

__device__ float4 g_W[40];   // (layer, qubit) -> (ar, ai, br, bi) of RZ*RY*RX

__global__ void prep_kernel(const float* __restrict__ w) {
    int t = blockIdx.x * blockDim.x + threadIdx.x;
    if (t >= 40) return;
    float a = w[t * 3 + 0], b = w[t * 3 + 1], c = w[t * 3 + 2];
    float sa, ca, sb, cb, sc, cc;
    sincosf(0.5f * a, &sa, &ca);
    sincosf(0.5f * b, &sb, &cb);
    sincosf(0.5f * c, &sc, &cc);
    // RX: a=(ca,0)  b=(0,-sa)
    // RY: a=(cb,0)  b=(-sb,0)
    // M = RY*RX:
    float m_ar = cb * ca;
    float m_ai = sb * sa;
    float m_br = -sb * ca;
    float m_bi = -cb * sa;
    // U = RZ*M with az = (cc, -sc), bz = 0:  alpha = az*am, beta = az*bm
    float u_ar = cc * m_ar + sc * m_ai;
    float u_ai = cc * m_ai - sc * m_ar;
    float u_br = cc * m_br + sc * m_bi;
    float u_bi = cc * m_bi - sc * m_br;
    g_W[t] = make_float4(u_ar, u_ai, u_br, u_bi);
}

// Apply general SU(2) on local bit M (pure register math)
template<int M>
__device__ __forceinline__ void u_local(float (&xr)[32], float (&xi)[32],
                                        float ar, float ai, float br, float bi) {
#pragma unroll
    for (int l = 0; l < 32; ++l) if (!(l & M)) {
        const int h = l | M;
        float r0 = xr[l], i0 = xi[l], r1 = xr[h], i1 = xi[h];
        xr[l] =  ar * r0 - ai * i0 + br * r1 - bi * i1;
        xi[l] =  ar * i0 + ai * r0 + br * i1 + bi * r1;
        xr[h] = -br * r0 - bi * i0 + ar * r1 + ai * i1;
        xi[h] = -br * i0 + bi * r0 + ar * i1 - ai * r1;
    }
}

// Apply general SU(2) on lane bit K (shuffle form).
// Row for this lane: bit=0 -> diag=(ar,ai), off=(br,bi)
//                    bit=1 -> diag=(ar,-ai), off=(-br,bi)
template<int K>
__device__ __forceinline__ void u_lane(float (&xr)[32], float (&xi)[32],
                                       float ar, float ai, float br, float bi,
                                       unsigned lane) {
    const bool hi = (lane & K) != 0;
    const float di = hi ? -ai : ai;
    const float orr = hi ? -br : br;
#pragma unroll
    for (int l = 0; l < 32; ++l) {
        float pr = __shfl_xor_sync(FULL, xr[l], K);
        float pi = __shfl_xor_sync(FULL, xi[l], K);
        float vr = xr[l], vi = xi[l];
        xr[l] = ar * vr - di * vi + orr * pr - bi * pi;
        xi[l] = ar * vi + di * vr + orr * pi + bi * pr;
    }
}

// Composed CNOT(0,1)(1,2)(2,3)(3,4) on lane bits: one idx-shuffle pass.
// Inverse index map: src = lane ^ (lane >> 1).
__device__ __forceinline__ void cnot_ring_lanes(float (&xr)[32], float (&xi)[32],
                                                unsigned lane) {
    const int src = (int)(lane ^ (lane >> 1));
#pragma unroll
    for (int l = 0; l < 32; ++l) {
        xr[l] = __shfl_sync(FULL, xr[l], src);
        xi[l] = __shfl_sync(FULL, xi[l], src);
    }
}

// CNOT, control & target both local bits (pure register rename, free)
template<int CM, int TM>
__device__ __forceinline__ void cnot_ll(float (&xr)[32], float (&xi)[32]) {
#pragma unroll
    for (int l = 0; l < 32; ++l) if ((l & CM) && !(l & TM)) {
        const int h = l | TM;
        float tr = xr[l]; xr[l] = xr[h]; xr[h] = tr;
        float ti = xi[l]; xi[l] = xi[h]; xi[h] = ti;
    }
}

__global__ void __launch_bounds__(256)
qsim_kernel(const float* __restrict__ x, float* __restrict__ out)
{
    const unsigned lane = threadIdx.x & 31u;
    const int warp = blockIdx.x * (blockDim.x >> 5) + (threadIdx.x >> 5);
    const float* xb = x + warp * 10;

    // Data-encoding half-angle cos/sin (reused every layer)
    float cx[10], sx[10];
#pragma unroll
    for (int q = 0; q < 10; ++q) {
        float v = fminf(fmaxf(xb[q], -PI_F), PI_F);
        __sincosf(0.5f * v, &sx[q], &cx[q]);
    }

    float xr[32], xi[32];
#pragma unroll
    for (int l = 0; l < 32; ++l) { xr[l] = 0.f; xi[l] = 0.f; }
    if (lane == 0) xr[0] = 1.f;

    for (int layer = 0; layer < 4; ++layer) {
        // Fused U_q = W_q * RY(x_q), W from prep kernel, RY(x)=(c, -s) real.
        // alpha = aw*c + bw*s ; beta = bw*c - aw*s   (componentwise)
#define GATE(Q, APPLY)                                                  \
        {                                                               \
            float4 wq = g_W[layer * 10 + (Q)];                          \
            float c = cx[Q], s = sx[Q];                                 \
            float ar = wq.x * c + wq.z * s;                             \
            float ai = wq.y * c + wq.w * s;                             \
            float br = wq.z * c - wq.x * s;                             \
            float bi = wq.w * c - wq.y * s;                             \
            APPLY;                                                      \
        }
        GATE(0, (u_lane<16>(xr, xi, ar, ai, br, bi, lane)))
        GATE(1, (u_lane< 8>(xr, xi, ar, ai, br, bi, lane)))
        GATE(2, (u_lane< 4>(xr, xi, ar, ai, br, bi, lane)))
        GATE(3, (u_lane< 2>(xr, xi, ar, ai, br, bi, lane)))
        GATE(4, (u_lane< 1>(xr, xi, ar, ai, br, bi, lane)))
        GATE(5, (u_local<16>(xr, xi, ar, ai, br, bi)))
        GATE(6, (u_local< 8>(xr, xi, ar, ai, br, bi)))
        GATE(7, (u_local< 4>(xr, xi, ar, ai, br, bi)))
        GATE(8, (u_local< 2>(xr, xi, ar, ai, br, bi)))
        GATE(9, (u_local< 1>(xr, xi, ar, ai, br, bi)))
#undef GATE

        // CNOT ring. (0,1)(1,2)(2,3)(3,4) fused into one permutation pass.
        cnot_ring_lanes(xr, xi, lane);
        // (4,5): control = qubit4 = lane bit0, target = local bit 16
        if (lane & 1) {
#pragma unroll
            for (int l = 0; l < 16; ++l) {
                const int h = l | 16;
                float tr = xr[l]; xr[l] = xr[h]; xr[h] = tr;
                float ti = xi[l]; xi[l] = xi[h]; xi[h] = ti;
            }
        }
        // (5,6)(6,7)(7,8)(8,9): free register renames
        cnot_ll<16, 8>(xr, xi);
        cnot_ll< 8, 4>(xr, xi);
        cnot_ll< 4, 2>(xr, xi);
        cnot_ll< 2, 1>(xr, xi);
        // (9,0): control = local bit0, target = lane bit 16
#pragma unroll
        for (int l = 0; l < 32; ++l) if (l & 1) {
            xr[l] = __shfl_xor_sync(FULL, xr[l], 16);
            xi[l] = __shfl_xor_sync(FULL, xi[l], 16);
        }
    }

    // -- measurement: <Z_q> --
    float tot = 0.f, z5 = 0.f, z6 = 0.f, z7 = 0.f, z8 = 0.f, z9 = 0.f;
#pragma unroll
    for (int l = 0; l < 32; ++l) {
        float p = xr[l] * xr[l] + xi[l] * xi[l];
        tot += p;
        z5 += (l & 16) ? -p : p;
        z6 += (l &  8) ? -p : p;
        z7 += (l &  4) ? -p : p;
        z8 += (l &  2) ? -p : p;
        z9 += (l &  1) ? -p : p;
    }
    float z[10];
    z[0] = (lane & 16) ? -tot : tot;
    z[1] = (lane &  8) ? -tot : tot;
    z[2] = (lane &  4) ? -tot : tot;
    z[3] = (lane &  2) ? -tot : tot;
    z[4] = (lane &  1) ? -tot : tot;
    z[5] = z5; z[6] = z6; z[7] = z7; z[8] = z8; z[9] = z9;

#pragma unroll
    for (int q = 0; q < 10; ++q) {
#pragma unroll
        for (int k = 16; k >= 1; k >>= 1)
            z[q] += __shfl_xor_sync(FULL, z[q], k);
    }
    if (lane == 0) {
#pragma unroll
        for (int q = 0; q < 10; ++q)
            out[warp * 10 + q] = z[q];
    }
}

extern "C" void kernel_launch(void* const* d_in, const int* in_sizes, int n_in,
                              void* d_out, int out_size) {
    const float* a = (const float*)d_in[0];
    const float* b = (const float*)d_in[1];
    const float* x = a;
    const float* w = b;
    if (n_in >= 2 && in_sizes[0] == 120 && in_sizes[1] == 40960) { x = b; w = a; }
    float* out = (float*)d_out;
    prep_kernel<<<1, 64>>>(w);
    qsim_kernel<<<512, 256>>>(x, out);
}

// round 3
// speedup vs baseline: 2.6139x; 1.3991x over previous
#include <cuda_runtime.h>

typedef unsigned long long u64;
#define PI_F 3.14159265358979323846f
#define FULL 0xffffffffu

// ---------------------------------------------------------------------------
// State layout (per warp = one batch element, 1024 complex amps):
//   amp index i = (lane << 5) | (k << 1) | c
//   qubits 0..4 -> lane bits 4..0 (lane mask K = 1 << (4-q))
//   qubits 5..8 -> k bits 3..0   (k mask MK = 1 << (8-q))
//   qubit  9    -> pack component c
// State stored as f32x2 packs: Xr[16], Xi[16]; pack k = (amp 2k, amp 2k+1).
// All gates are SU(2) [[a,b],[-conj b, conj a]]. Per layer per qubit the block
// RZ(w2)*RY(w1)*RX(w0)*RY(x_q) is one SU(2); weight part precomputed once.
// ---------------------------------------------------------------------------

__device__ float4 g_W[40];   // (layer, qubit) -> (ar, ai, br, bi) of RZ*RY*RX

__global__ void prep_kernel(const float* __restrict__ w) {
    int t = blockIdx.x * blockDim.x + threadIdx.x;
    if (t >= 40) return;
    float a = w[t * 3 + 0], b = w[t * 3 + 1], c = w[t * 3 + 2];
    float sa, ca, sb, cb, sc, cc;
    sincosf(0.5f * a, &sa, &ca);
    sincosf(0.5f * b, &sb, &cb);
    sincosf(0.5f * c, &sc, &cc);
    float m_ar = cb * ca, m_ai = sb * sa, m_br = -sb * ca, m_bi = -cb * sa;
    float u_ar = cc * m_ar + sc * m_ai;
    float u_ai = cc * m_ai - sc * m_ar;
    float u_br = cc * m_br + sc * m_bi;
    float u_bi = cc * m_bi - sc * m_br;
    g_W[t] = make_float4(u_ar, u_ai, u_br, u_bi);
}

// ---- f32x2 helpers (sm_100a packed fp32) ----
__device__ __forceinline__ u64 pk(float lo, float hi) {
    u64 r; asm("mov.b64 %0, {%1, %2};" : "=l"(r) : "f"(lo), "f"(hi)); return r;
}
__device__ __forceinline__ void unpk(u64 v, float& lo, float& hi) {
    asm("mov.b64 {%0, %1}, %2;" : "=f"(lo), "=f"(hi) : "l"(v));
}
__device__ __forceinline__ u64 dup2(float x) { return pk(x, x); }
__device__ __forceinline__ u64 f2fma(u64 a, u64 b, u64 c) {
    u64 d; asm("fma.rn.f32x2 %0, %1, %2, %3;" : "=l"(d) : "l"(a), "l"(b), "l"(c)); return d;
}
__device__ __forceinline__ u64 f2mul(u64 a, u64 b) {
    u64 d; asm("mul.rn.f32x2 %0, %1, %2;" : "=l"(d) : "l"(a), "l"(b)); return d;
}
__device__ __forceinline__ u64 f2add(u64 a, u64 b) {
    u64 d; asm("add.rn.f32x2 %0, %1, %2;" : "=l"(d) : "l"(a), "l"(b)); return d;
}
__device__ __forceinline__ u64 swap2(u64 v) {
    float a, b; unpk(v, a, b); return pk(b, a);
}
__device__ __forceinline__ u64 shflx2(u64 v, int m) {
    float a, b; unpk(v, a, b);
    a = __shfl_xor_sync(FULL, a, m);
    b = __shfl_xor_sync(FULL, b, m);
    return pk(a, b);
}
__device__ __forceinline__ u64 shfli2(u64 v, int s) {
    float a, b; unpk(v, a, b);
    a = __shfl_sync(FULL, a, s);
    b = __shfl_sync(FULL, b, s);
    return pk(a, b);
}

// ---- SU(2) on lane bit K (qubits 0..4): coefficients uniform per pack ----
template<int K>
__device__ __forceinline__ void u_lane(u64 (&Xr)[16], u64 (&Xi)[16],
                                       float ar, float ai, float br, float bi,
                                       unsigned lane) {
    const bool hi = (lane & K) != 0;
    const float di = hi ? -ai : ai;
    const float orr = hi ? -br : br;
    const u64 ar2 = dup2(ar), di2 = dup2(di), ndi2 = dup2(-di);
    const u64 or2 = dup2(orr), bi2 = dup2(bi), nbi2 = dup2(-bi);
#pragma unroll
    for (int k = 0; k < 16; ++k) {
        u64 Pr = shflx2(Xr[k], K);
        u64 Pi = shflx2(Xi[k], K);
        u64 nr = f2fma(ar2, Xr[k], f2fma(ndi2, Xi[k], f2fma(or2, Pr, f2mul(nbi2, Pi))));
        u64 ni = f2fma(ar2, Xi[k], f2fma(di2, Xr[k], f2fma(or2, Pi, f2mul(bi2, Pr))));
        Xr[k] = nr; Xi[k] = ni;
    }
}

// ---- SU(2) on k-space bit MK (qubits 5..8): pack-pair, swap-free ----
template<int MK>
__device__ __forceinline__ void u_localk(u64 (&Xr)[16], u64 (&Xi)[16],
                                         float ar, float ai, float br, float bi) {
    const u64 ar2 = dup2(ar), ai2 = dup2(ai), br2 = dup2(br), bi2 = dup2(bi);
    const u64 nai2 = dup2(-ai), nbr2 = dup2(-br), nbi2 = dup2(-bi);
#pragma unroll
    for (int k = 0; k < 16; ++k) if (!(k & MK)) {
        const int h = k | MK;
        u64 Ar = Xr[k], Ai = Xi[k], Br = Xr[h], Bi = Xi[h];
        Xr[k] = f2fma(ar2,  Ar, f2fma(nai2, Ai, f2fma(br2,  Br, f2mul(nbi2, Bi))));
        Xi[k] = f2fma(ai2,  Ar, f2fma(ar2,  Ai, f2fma(bi2,  Br, f2mul(br2,  Bi))));
        Xr[h] = f2fma(nbr2, Ar, f2fma(nbi2, Ai, f2fma(ar2,  Br, f2mul(ai2,  Bi))));
        Xi[h] = f2fma(bi2,  Ar, f2fma(nbr2, Ai, f2fma(nai2, Br, f2mul(ar2,  Bi))));
    }
}

// ---- SU(2) on qubit 9 (within-pack component) ----
__device__ __forceinline__ void u_q9(u64 (&Xr)[16], u64 (&Xi)[16],
                                     float ar, float ai, float br, float bi) {
    const u64 ar2 = dup2(ar);
    const u64 brm = pk(br, -br);
    const u64 aim = pk(-ai, ai);
    const u64 aim2 = pk(ai, -ai);
    const u64 bin = dup2(-bi);
    const u64 bi2 = dup2(bi);
#pragma unroll
    for (int k = 0; k < 16; ++k) {
        u64 sR = swap2(Xr[k]);
        u64 sI = swap2(Xi[k]);
        u64 nr = f2fma(ar2, Xr[k], f2fma(brm, sR, f2fma(aim,  Xi[k], f2mul(bin, sI))));
        u64 ni = f2fma(ar2, Xi[k], f2fma(brm, sI, f2fma(aim2, Xr[k], f2mul(bi2, sR))));
        Xr[k] = nr; Xi[k] = ni;
    }
}

// ---- CNOT in k-space (control & target among qubits 5..8): register renames
template<int CM, int TM>
__device__ __forceinline__ void cnot_kk(u64 (&Xr)[16], u64 (&Xi)[16]) {
#pragma unroll
    for (int k = 0; k < 16; ++k) if ((k & CM) && !(k & TM)) {
        const int h = k | TM;
        u64 t = Xr[k]; Xr[k] = Xr[h]; Xr[h] = t;
        t = Xi[k]; Xi[k] = Xi[h]; Xi[h] = t;
    }
}

__global__ void __launch_bounds__(128, 4)
qsim_kernel(const float* __restrict__ x, float* __restrict__ out)
{
    const unsigned lane = threadIdx.x & 31u;
    const int warp = blockIdx.x * (blockDim.x >> 5) + (threadIdx.x >> 5);
    const float* xb = x + warp * 10;

    // Data-encoding half-angle cos/sin (reused every layer)
    float cx[10], sx[10];
#pragma unroll
    for (int q = 0; q < 10; ++q) {
        float v = fminf(fmaxf(xb[q], -PI_F), PI_F);
        __sincosf(0.5f * v, &sx[q], &cx[q]);
    }

    u64 Xr[16], Xi[16];
#pragma unroll
    for (int k = 0; k < 16; ++k) { Xr[k] = 0ull; Xi[k] = 0ull; }
    if (lane == 0) Xr[0] = pk(1.0f, 0.0f);

    for (int layer = 0; layer < 4; ++layer) {
        // Fused U_q = W_q * RY(x_q); RY(x) = (c, -s) real SU(2).
#define GATE(Q, APPLY)                                                  \
        {                                                               \
            float4 wq = g_W[layer * 10 + (Q)];                          \
            float c = cx[Q], s = sx[Q];                                 \
            float ar = wq.x * c + wq.z * s;                             \
            float ai = wq.y * c + wq.w * s;                             \
            float br = wq.z * c - wq.x * s;                             \
            float bi = wq.w * c - wq.y * s;                             \
            APPLY;                                                      \
        }
        GATE(0, (u_lane<16>(Xr, Xi, ar, ai, br, bi, lane)))
        GATE(1, (u_lane< 8>(Xr, Xi, ar, ai, br, bi, lane)))
        GATE(2, (u_lane< 4>(Xr, Xi, ar, ai, br, bi, lane)))
        GATE(3, (u_lane< 2>(Xr, Xi, ar, ai, br, bi, lane)))
        GATE(4, (u_lane< 1>(Xr, Xi, ar, ai, br, bi, lane)))
        GATE(5, (u_localk<8>(Xr, Xi, ar, ai, br, bi)))
        GATE(6, (u_localk<4>(Xr, Xi, ar, ai, br, bi)))
        GATE(7, (u_localk<2>(Xr, Xi, ar, ai, br, bi)))
        GATE(8, (u_localk<1>(Xr, Xi, ar, ai, br, bi)))
        GATE(9, (u_q9(Xr, Xi, ar, ai, br, bi)))
#undef GATE

        // CNOT ring.
        // (0,1)(1,2)(2,3)(3,4) fused: prefix-xor lane permutation, src = lane^(lane>>1)
        {
            const int src = (int)(lane ^ (lane >> 1));
#pragma unroll
            for (int k = 0; k < 16; ++k) {
                Xr[k] = shfli2(Xr[k], src);
                Xi[k] = shfli2(Xi[k], src);
            }
        }
        // (4,5): control = qubit4 = lane bit0, target = k bit 8
        if (lane & 1) {
#pragma unroll
            for (int k = 0; k < 8; ++k) {
                const int h = k | 8;
                u64 t = Xr[k]; Xr[k] = Xr[h]; Xr[h] = t;
                t = Xi[k]; Xi[k] = Xi[h]; Xi[h] = t;
            }
        }
        // (5,6)(6,7)(7,8): k-space renames
        cnot_kk<8, 4>(Xr, Xi);
        cnot_kk<4, 2>(Xr, Xi);
        cnot_kk<2, 1>(Xr, Xi);
        // (8,9): control = k bit0, target = pack component
#pragma unroll
        for (int k = 1; k < 16; k += 2) {
            Xr[k] = swap2(Xr[k]);
            Xi[k] = swap2(Xi[k]);
        }
        // (9,0): control = component 1, target = lane bit 16
#pragma unroll
        for (int k = 0; k < 16; ++k) {
            float l0, h0;
            unpk(Xr[k], l0, h0);
            h0 = __shfl_xor_sync(FULL, h0, 16);
            Xr[k] = pk(l0, h0);
            unpk(Xi[k], l0, h0);
            h0 = __shfl_xor_sync(FULL, h0, 16);
            Xi[k] = pk(l0, h0);
        }
    }

    // ---- measurement: <Z_q>, fully packed accumulation ----
    u64 tot2 = 0ull, s5 = 0ull, s6 = 0ull, s7 = 0ull, s8 = 0ull;
    const u64 N1 = dup2(-1.0f);
#pragma unroll
    for (int k = 0; k < 16; ++k) {
        u64 P = f2fma(Xr[k], Xr[k], f2mul(Xi[k], Xi[k]));
        tot2 = f2add(tot2, P);
        s5 = (k & 8) ? f2fma(P, N1, s5) : f2add(s5, P);
        s6 = (k & 4) ? f2fma(P, N1, s6) : f2add(s6, P);
        s7 = (k & 2) ? f2fma(P, N1, s7) : f2add(s7, P);
        s8 = (k & 1) ? f2fma(P, N1, s8) : f2add(s8, P);
    }
    float tl, th;
    unpk(tot2, tl, th);
    const float tot = tl + th;
    float z[10];
    z[0] = (lane & 16) ? -tot : tot;
    z[1] = (lane &  8) ? -tot : tot;
    z[2] = (lane &  4) ? -tot : tot;
    z[3] = (lane &  2) ? -tot : tot;
    z[4] = (lane &  1) ? -tot : tot;
    { float a, b; unpk(s5, a, b); z[5] = a + b; }
    { float a, b; unpk(s6, a, b); z[6] = a + b; }
    { float a, b; unpk(s7, a, b); z[7] = a + b; }
    { float a, b; unpk(s8, a, b); z[8] = a + b; }
    z[9] = tl - th;

#pragma unroll
    for (int q = 0; q < 10; ++q) {
#pragma unroll
        for (int k = 16; k >= 1; k >>= 1)
            z[q] += __shfl_xor_sync(FULL, z[q], k);
    }
    if (lane == 0) {
#pragma unroll
        for (int q = 0; q < 10; ++q)
            out[warp * 10 + q] = z[q];
    }
}

extern "C" void kernel_launch(void* const* d_in, const int* in_sizes, int n_in,
                              void* d_out, int out_size) {
    const float* a = (const float*)d_in[0];
    const float* b = (const float*)d_in[1];
    const float* x = a;
    const float* w = b;
    if (n_in >= 2 && in_sizes[0] == 120 && in_sizes[1] == 40960) { x = b; w = a; }
    float* out = (float*)d_out;
    prep_kernel<<<1, 64>>>(w);
    qsim_kernel<<<1024, 128>>>(x, out);
}

// round 4
// speedup vs baseline: 2.7069x; 1.0356x over previous
#include <cuda_runtime.h>

typedef unsigned long long u64;
#define PI_F 3.14159265358979323846f
#define FULL 0xffffffffu

// ---------------------------------------------------------------------------
// State layout (per warp = one batch element, 1024 complex amps):
//   amp index i = (lane' << 5) | (k << 1) | c     (lane' = LOGICAL lane index)
//   qubits 0..4 -> logical lane bits 4..0 (mask 16>>q)
//   qubits 5..8 -> k bits 3..0 (mask 8>>(q-5))
//   qubit  9    -> pack component c
// State stored as f32x2 packs Xr[16], Xi[16].
//
// The CNOT ring's lane part (0,1)(1,2)(2,3)(3,4) is the linear permutation
// new[n] = old[g(n)], g(n) = n ^ (n>>1). We never move data for it: each
// thread tracks its logical index p = P(lane), P <- ginv o P per layer, and
// since P is GF(2)-linear, a gate on logical mask K keeps the shfl.xor form
// with physical mask P^-1(K) = g^layer(K) (precomputed constants below).
//
// Layer 0 acts on |0..0>: the post-gate state is a product state, built
// directly (no gate applications, no shuffles).
// ---------------------------------------------------------------------------

__device__ float4 g_W[40];   // (layer, qubit) -> (ar, ai, br, bi) of RZ*RY*RX

__global__ void prep_kernel(const float* __restrict__ w) {
    int t = blockIdx.x * blockDim.x + threadIdx.x;
    if (t >= 40) return;
    float a = w[t * 3 + 0], b = w[t * 3 + 1], c = w[t * 3 + 2];
    float sa, ca, sb, cb, sc, cc;
    sincosf(0.5f * a, &sa, &ca);
    sincosf(0.5f * b, &sb, &cb);
    sincosf(0.5f * c, &sc, &cc);
    float m_ar = cb * ca, m_ai = sb * sa, m_br = -sb * ca, m_bi = -cb * sa;
    float u_ar = cc * m_ar + sc * m_ai;
    float u_ai = cc * m_ai - sc * m_ar;
    float u_br = cc * m_br + sc * m_bi;
    float u_bi = cc * m_bi - sc * m_br;
    g_W[t] = make_float4(u_ar, u_ai, u_br, u_bi);
}

// ---- f32x2 helpers ----
__device__ __forceinline__ u64 pk(float lo, float hi) {
    u64 r; asm("mov.b64 %0, {%1, %2};" : "=l"(r) : "f"(lo), "f"(hi)); return r;
}
__device__ __forceinline__ void unpk(u64 v, float& lo, float& hi) {
    asm("mov.b64 {%0, %1}, %2;" : "=f"(lo), "=f"(hi) : "l"(v));
}
__device__ __forceinline__ u64 dup2(float x) { return pk(x, x); }
__device__ __forceinline__ u64 f2fma(u64 a, u64 b, u64 c) {
    u64 d; asm("fma.rn.f32x2 %0, %1, %2, %3;" : "=l"(d) : "l"(a), "l"(b), "l"(c)); return d;
}
__device__ __forceinline__ u64 f2mul(u64 a, u64 b) {
    u64 d; asm("mul.rn.f32x2 %0, %1, %2;" : "=l"(d) : "l"(a), "l"(b)); return d;
}
__device__ __forceinline__ u64 f2add(u64 a, u64 b) {
    u64 d; asm("add.rn.f32x2 %0, %1, %2;" : "=l"(d) : "l"(a), "l"(b)); return d;
}
__device__ __forceinline__ u64 swap2(u64 v) {
    float a, b; unpk(v, a, b); return pk(b, a);
}
__device__ __forceinline__ u64 shflx2(u64 v, int m) {
    float a, b; unpk(v, a, b);
    a = __shfl_xor_sync(FULL, a, m);
    b = __shfl_xor_sync(FULL, b, m);
    return pk(a, b);
}

// inverse of g(n)=n^(n>>1) on 5 bits (prefix-xor)
__device__ __forceinline__ int ginv5(int n) {
    n ^= n >> 1; n ^= n >> 2; n ^= n >> 4;
    return n & 31;
}

// ---- SU(2) on a lane qubit: physical shfl mask KS, logical row-select hi ----
__device__ __forceinline__ void u_lane(u64 (&Xr)[16], u64 (&Xi)[16],
                                       float ar, float ai, float br, float bi,
                                       bool hi, int KS) {
    const float di = hi ? -ai : ai;
    const float orr = hi ? -br : br;
    const u64 ar2 = dup2(ar), di2 = dup2(di), ndi2 = dup2(-di);
    const u64 or2 = dup2(orr), bi2 = dup2(bi), nbi2 = dup2(-bi);
#pragma unroll
    for (int k = 0; k < 16; ++k) {
        u64 Pr = shflx2(Xr[k], KS);
        u64 Pi = shflx2(Xi[k], KS);
        u64 nr = f2fma(ar2, Xr[k], f2fma(ndi2, Xi[k], f2fma(or2, Pr, f2mul(nbi2, Pi))));
        u64 ni = f2fma(ar2, Xi[k], f2fma(di2, Xr[k], f2fma(or2, Pi, f2mul(bi2, Pr))));
        Xr[k] = nr; Xi[k] = ni;
    }
}

// ---- SU(2) on k-space bit MK (qubits 5..8) ----
template<int MK>
__device__ __forceinline__ void u_localk(u64 (&Xr)[16], u64 (&Xi)[16],
                                         float ar, float ai, float br, float bi) {
    const u64 ar2 = dup2(ar), ai2 = dup2(ai), br2 = dup2(br), bi2 = dup2(bi);
    const u64 nai2 = dup2(-ai), nbr2 = dup2(-br), nbi2 = dup2(-bi);
#pragma unroll
    for (int k = 0; k < 16; ++k) if (!(k & MK)) {
        const int h = k | MK;
        u64 Ar = Xr[k], Ai = Xi[k], Br = Xr[h], Bi = Xi[h];
        Xr[k] = f2fma(ar2,  Ar, f2fma(nai2, Ai, f2fma(br2,  Br, f2mul(nbi2, Bi))));
        Xi[k] = f2fma(ai2,  Ar, f2fma(ar2,  Ai, f2fma(bi2,  Br, f2mul(br2,  Bi))));
        Xr[h] = f2fma(nbr2, Ar, f2fma(nbi2, Ai, f2fma(ar2,  Br, f2mul(ai2,  Bi))));
        Xi[h] = f2fma(bi2,  Ar, f2fma(nbr2, Ai, f2fma(nai2, Br, f2mul(ar2,  Bi))));
    }
}

// ---- SU(2) on qubit 9 (within-pack component) ----
__device__ __forceinline__ void u_q9(u64 (&Xr)[16], u64 (&Xi)[16],
                                     float ar, float ai, float br, float bi) {
    const u64 ar2 = dup2(ar);
    const u64 brm = pk(br, -br);
    const u64 aim = pk(-ai, ai);
    const u64 aim2 = pk(ai, -ai);
    const u64 bin = dup2(-bi);
    const u64 bi2 = dup2(bi);
#pragma unroll
    for (int k = 0; k < 16; ++k) {
        u64 sR = swap2(Xr[k]);
        u64 sI = swap2(Xi[k]);
        u64 nr = f2fma(ar2, Xr[k], f2fma(brm, sR, f2fma(aim,  Xi[k], f2mul(bin, sI))));
        u64 ni = f2fma(ar2, Xi[k], f2fma(brm, sI, f2fma(aim2, Xr[k], f2mul(bi2, sR))));
        Xr[k] = nr; Xi[k] = ni;
    }
}

template<int CM, int TM>
__device__ __forceinline__ void cnot_kk(u64 (&Xr)[16], u64 (&Xi)[16]) {
#pragma unroll
    for (int k = 0; k < 16; ++k) if ((k & CM) && !(k & TM)) {
        const int h = k | TM;
        u64 t = Xr[k]; Xr[k] = Xr[h]; Xr[h] = t;
        t = Xi[k]; Xi[k] = Xi[h]; Xi[h] = t;
    }
}

// CNOT ring tail: (4,5) cond swap, k renames, (8,9), (9,0) with physical mask
__device__ __forceinline__ void ring_tail(u64 (&Xr)[16], u64 (&Xi)[16],
                                          bool c45, int m90) {
    if (c45) {
#pragma unroll
        for (int k = 0; k < 8; ++k) {
            const int h = k | 8;
            u64 t = Xr[k]; Xr[k] = Xr[h]; Xr[h] = t;
            t = Xi[k]; Xi[k] = Xi[h]; Xi[h] = t;
        }
    }
    cnot_kk<8, 4>(Xr, Xi);
    cnot_kk<4, 2>(Xr, Xi);
    cnot_kk<2, 1>(Xr, Xi);
#pragma unroll
    for (int k = 1; k < 16; k += 2) {
        Xr[k] = swap2(Xr[k]);
        Xi[k] = swap2(Xi[k]);
    }
#pragma unroll
    for (int k = 0; k < 16; ++k) {
        float l0, h0;
        unpk(Xr[k], l0, h0);
        h0 = __shfl_xor_sync(FULL, h0, m90);
        Xr[k] = pk(l0, h0);
        unpk(Xi[k], l0, h0);
        h0 = __shfl_xor_sync(FULL, h0, m90);
        Xi[k] = pk(l0, h0);
    }
}

__global__ void __launch_bounds__(128, 4)
qsim_kernel(const float* __restrict__ x, float* __restrict__ out)
{
    const unsigned lane = threadIdx.x & 31u;
    const int warp = blockIdx.x * (blockDim.x >> 5) + (threadIdx.x >> 5);
    const float* xb = x + warp * 10;

    float cx[10], sx[10];
#pragma unroll
    for (int q = 0; q < 10; ++q) {
        float v = fminf(fmaxf(xb[q], -PI_F), PI_F);
        __sincosf(0.5f * v, &sx[q], &cx[q]);
    }

    u64 Xr[16], Xi[16];

    // ======== layer 0: direct product-state construction ========
    // U_q|0> = (alpha, -conj(beta)) = ((ar,ai), (-br, bi))
    {
        float var[10], vai[10], vwr[10], vwi[10];
#pragma unroll
        for (int q = 0; q < 10; ++q) {
            float4 wq = g_W[q];
            float c = cx[q], s = sx[q];
            var[q] = wq.x * c + wq.z * s;
            vai[q] = wq.y * c + wq.w * s;
            vwr[q] = -(wq.z * c - wq.x * s);
            vwi[q] =  (wq.w * c - wq.y * s);
        }
        // lane factor over qubits 0..4 (identity labeling at layer 0)
        float Fr, Fi;
        { bool b = (lane & 16) != 0; Fr = b ? vwr[0] : var[0]; Fi = b ? vwi[0] : vai[0]; }
#pragma unroll
        for (int q = 1; q < 5; ++q) {
            bool b = (lane & (16u >> q)) != 0;
            float er = b ? vwr[q] : var[q], ei = b ? vwi[q] : vai[q];
            float nr = Fr * er - Fi * ei;
            float ni = Fr * ei + Fi * er;
            Fr = nr; Fi = ni;
        }
        // q9 as the pack component, combined with F
        u64 B0r = pk(var[9], vwr[9]);
        u64 B0i = pk(vai[9], vwi[9]);
        u64 Fr2 = dup2(Fr), Fi2 = dup2(Fi), nFi2 = dup2(-Fi);
        u64 FBr = f2fma(Fr2, B0r, f2mul(nFi2, B0i));
        u64 FBi = f2fma(Fr2, B0i, f2mul(Fi2, B0r));
        // product tree over q5(k bit3), q6(bit2), q7(bit1), q8(bit0)
        float c2r[2] = {var[5], vwr[5]}, c2i[2] = {vai[5], vwi[5]};
        float c4r[4], c4i[4];
#pragma unroll
        for (int j = 0; j < 4; ++j) {
            float er = (j & 1) ? vwr[6] : var[6], ei = (j & 1) ? vwi[6] : vai[6];
            int h = j >> 1;
            c4r[j] = c2r[h] * er - c2i[h] * ei;
            c4i[j] = c2r[h] * ei + c2i[h] * er;
        }
        float c8r[8], c8i[8];
#pragma unroll
        for (int j = 0; j < 8; ++j) {
            float er = (j & 1) ? vwr[7] : var[7], ei = (j & 1) ? vwi[7] : vai[7];
            int h = j >> 1;
            c8r[j] = c4r[h] * er - c4i[h] * ei;
            c8i[j] = c4r[h] * ei + c4i[h] * er;
        }
#pragma unroll
        for (int k = 0; k < 16; ++k) {
            float er = (k & 1) ? vwr[8] : var[8], ei = (k & 1) ? vwi[8] : vai[8];
            int h = k >> 1;
            float mr = c8r[h] * er - c8i[h] * ei;
            float mi = c8r[h] * ei + c8i[h] * er;
            u64 mr2 = dup2(mr), mi2 = dup2(mi), nmi2 = dup2(-mi);
            Xr[k] = f2fma(mr2, FBr, f2mul(nmi2, FBi));
            Xi[k] = f2fma(mr2, FBi, f2mul(mi2, FBr));
        }
    }

    // layer-0 CNOT ring: lane part is a relabel; tail applied physically
    int p = ginv5((int)lane);                 // logical index of this thread
    ring_tail(Xr, Xi, (p & 1) != 0, 24);      // m90 = g^1(16) = 24

    // physical shfl masks g^L(K) for logical K = 16>>q, and g^{L+1}(16)
    const int LM[4][5] = {{16,8,4,2,1},{24,12,6,3,1},{20,10,5,2,1},{30,15,7,3,1}};
    const int M90[4] = {24, 20, 30, 17};

    // ======== layers 1..3: full gate applications ========
#pragma unroll
    for (int L = 1; L < 4; ++L) {
#define GATEC(Q)                                                   \
            float4 wq = g_W[L * 10 + (Q)];                         \
            float c = cx[Q], s = sx[Q];                            \
            float ar = wq.x * c + wq.z * s;                        \
            float ai = wq.y * c + wq.w * s;                        \
            float br = wq.z * c - wq.x * s;                        \
            float bi = wq.w * c - wq.y * s;
        { GATEC(0) u_lane(Xr, Xi, ar, ai, br, bi, (p & 16) != 0, LM[L][0]); }
        { GATEC(1) u_lane(Xr, Xi, ar, ai, br, bi, (p &  8) != 0, LM[L][1]); }
        { GATEC(2) u_lane(Xr, Xi, ar, ai, br, bi, (p &  4) != 0, LM[L][2]); }
        { GATEC(3) u_lane(Xr, Xi, ar, ai, br, bi, (p &  2) != 0, LM[L][3]); }
        { GATEC(4) u_lane(Xr, Xi, ar, ai, br, bi, (p &  1) != 0, LM[L][4]); }
        { GATEC(5) u_localk<8>(Xr, Xi, ar, ai, br, bi); }
        { GATEC(6) u_localk<4>(Xr, Xi, ar, ai, br, bi); }
        { GATEC(7) u_localk<2>(Xr, Xi, ar, ai, br, bi); }
        { GATEC(8) u_localk<1>(Xr, Xi, ar, ai, br, bi); }
        { GATEC(9) u_q9(Xr, Xi, ar, ai, br, bi); }
#undef GATEC
        p = ginv5(p);                          // lane ring as relabel
        ring_tail(Xr, Xi, (p & 1) != 0, M90[L]);
    }

    // ======== measurement: <Z_q> ========
    u64 tot2 = 0ull, s5 = 0ull, s6 = 0ull, s7 = 0ull, s8 = 0ull;
    const u64 N1 = dup2(-1.0f);
#pragma unroll
    for (int k = 0; k < 16; ++k) {
        u64 P = f2fma(Xr[k], Xr[k], f2mul(Xi[k], Xi[k]));
        tot2 = f2add(tot2, P);
        s5 = (k & 8) ? f2fma(P, N1, s5) : f2add(s5, P);
        s6 = (k & 4) ? f2fma(P, N1, s6) : f2add(s6, P);
        s7 = (k & 2) ? f2fma(P, N1, s7) : f2add(s7, P);
        s8 = (k & 1) ? f2fma(P, N1, s8) : f2add(s8, P);
    }
    float tl, th;
    unpk(tot2, tl, th);
    const float tot = tl + th;
    float z[10];
    z[0] = (p & 16) ? -tot : tot;
    z[1] = (p &  8) ? -tot : tot;
    z[2] = (p &  4) ? -tot : tot;
    z[3] = (p &  2) ? -tot : tot;
    z[4] = (p &  1) ? -tot : tot;
    { float a, b; unpk(s5, a, b); z[5] = a + b; }
    { float a, b; unpk(s6, a, b); z[6] = a + b; }
    { float a, b; unpk(s7, a, b); z[7] = a + b; }
    { float a, b; unpk(s8, a, b); z[8] = a + b; }
    z[9] = tl - th;

#pragma unroll
    for (int q = 0; q < 10; ++q) {
#pragma unroll
        for (int k = 16; k >= 1; k >>= 1)
            z[q] += __shfl_xor_sync(FULL, z[q], k);
    }
    if (lane == 0) {
#pragma unroll
        for (int q = 0; q < 10; ++q)
            out[warp * 10 + q] = z[q];
    }
}

extern "C" void kernel_launch(void* const* d_in, const int* in_sizes, int n_in,
                              void* d_out, int out_size) {
    const float* a = (const float*)d_in[0];
    const float* b = (const float*)d_in[1];
    const float* x = a;
    const float* w = b;
    if (n_in >= 2 && in_sizes[0] == 120 && in_sizes[1] == 40960) { x = b; w = a; }
    float* out = (float*)d_out;
    prep_kernel<<<1, 64>>>(w);
    qsim_kernel<<<1024, 128>>>(x, out);
}